// round 15
// baseline (speedup 1.0000x reference)
#include <cuda_runtime.h>
#include <cstdint>

// ---------------- problem constants ----------------
#define BB      8
#define HEADS   4
#define NQ      3136
#define NKV     784
#define DH      32
#define CC      128
#define TN      64                 // kv tile (12 full tiles + tail of 16)
#define NFULL   12
#define VSTRIDE 26624              // 13 tiles * 2048 floats per (b,h)
#define QPB64   ((BB * NQ) / 64)   // 392
#define KVB64   ((BB * NKV) / 64)  // 98

typedef unsigned long long u64;

// ---------------- scratch (device globals; no allocation) ----------------
__device__ float g_q [BB * HEADS * NQ  * DH];      // permuted d', tf32, scaled by 32^-.5*log2e
__device__ float g_k [BB * HEADS * NKV * DH];      // permuted d', tf32
__device__ float g_v [BB * HEADS * VSTRIDE];       // sigma-permuted Vp, tf32
__device__ float g_xr[BB * NKV * CC];
__device__ float g_ao[BB * NQ  * CC];

// ---------------- helpers ----------------
__device__ __forceinline__ float to_tf32(float x) {
    float r; asm("cvt.rna.tf32.f32 %0, %1;" : "=f"(r) : "f"(x)); return r;
}
__device__ __forceinline__ float ex2(float x) {
    float r; asm("ex2.approx.f32 %0, %1;" : "=f"(r) : "f"(x)); return r;
}
__device__ __forceinline__ unsigned smem_u32(const void* p) {
    return (unsigned)__cvta_generic_to_shared(p);
}
__device__ __forceinline__ void cp16(unsigned dst, const void* src) {
    asm volatile("cp.async.cg.shared.global [%0], [%1], 16;\n" :: "r"(dst), "l"(src));
}
__device__ __forceinline__ void cp_commit() {
    asm volatile("cp.async.commit_group;\n" ::: "memory");
}
__device__ __forceinline__ void cp_wait0() {
    asm volatile("cp.async.wait_group 0;\n" ::: "memory");
}
__device__ __forceinline__ void cp_wait1() {
    asm volatile("cp.async.wait_group 1;\n" ::: "memory");
}

// mma.sync m16n8k8 tf32 (base PTX, sm_80+)
__device__ __forceinline__ void mma8(float c[4], float a0, float a1, float a2, float a3,
                                     float b0, float b1) {
    asm volatile(
        "mma.sync.aligned.m16n8k8.row.col.f32.tf32.tf32.f32 "
        "{%0,%1,%2,%3}, {%4,%5,%6,%7}, {%8,%9}, {%0,%1,%2,%3};"
        : "+f"(c[0]), "+f"(c[1]), "+f"(c[2]), "+f"(c[3])
        : "r"(__float_as_uint(a0)), "r"(__float_as_uint(a1)),
          "r"(__float_as_uint(a2)), "r"(__float_as_uint(a3)),
          "r"(__float_as_uint(b0)), "r"(__float_as_uint(b1)));
}

// ---------------- tensor-core projection: Y = X(64x128 tile) @ W + b ------
// CTA = 64 rows x 128 cols, 8 warps (2m x 4n). K chunks of 32.
// X staged by cp.async (coalesced) into raw-fp32 [64][36] buffers; A-scalars
// get cvt.rna at consume time. W register-staged (perm + XOR swizzle, tf32).
// One barrier per chunk.
// dynamic smem: Xs 2*2304 floats @0, Ws 2*4352 floats @4608. 53248 B.
#define PROJ_SMEM_B 53248
template<int MODE>
__device__ __forceinline__ void proj_mma_body64(
    const float* __restrict__ X, const float* __restrict__ W,
    const float* __restrict__ bias, float* __restrict__ Y, int rowb)
{
    extern __shared__ __align__(16) float psm[];
    float* Ws0 = psm + 4608;

    const int tid  = threadIdx.x;
    const int lane = tid & 31, w = tid >> 5;
    const int g = lane >> 2, t = lane & 3;
    const int mw  = (w & 1) * 32;
    const int nwq = (w >> 1) * 32;
    const int w4  = (w >> 1) * 4;
    const unsigned xs_base = smem_u32(psm);

    float o[2][4][4];
#pragma unroll
    for (int mf = 0; mf < 2; mf++)
#pragma unroll
        for (int j = 0; j < 4; j++)
#pragma unroll
            for (int c = 0; c < 4; c++) o[mf][j][c] = 0.f;

    float4 wa[4];
    auto cp_x = [&](int kc, int bf) {
#pragma unroll
        for (int i = 0; i < 2; i++) {
            int idx = tid + i * 256;
            int r = idx >> 3, c = idx & 7;
            cp16(xs_base + bf * 9216 + r * 144 + c * 16,
                 &X[(size_t)(rowb + r) * CC + kc + 4 * c]);
        }
        cp_commit();
    };
    auto load_w = [&](int kc) {
#pragma unroll
        for (int i = 0; i < 4; i++) {
            int vv = tid + i * 256;
            int kk = vv >> 5, ng = vv & 31;
            wa[i] = *(const float4*)&W[(size_t)(kc + kk) * CC + ng * 4];
        }
    };
    auto store_w = [&](int bf) {
#pragma unroll
        for (int i = 0; i < 4; i++) {
            int vv = tid + i * 256;
            int kk = vv >> 5, n0 = (vv & 31) * 4;
            float vals[4] = {to_tf32(wa[i].x), to_tf32(wa[i].y),
                             to_tf32(wa[i].z), to_tf32(wa[i].w)};
#pragma unroll
            for (int c2 = 0; c2 < 4; c2++) {
                int n = n0 + c2;
                int p = (n & 7) * 16 + (n >> 3);
                int sp = p ^ (((p >> 5) & 3) << 2);
                Ws0[bf * 4352 + kk * 136 + sp] = vals[c2];
            }
        }
    };

    // prologue: X0, X1 via cp.async; W0 staged; W1 in regs
    load_w(0);
    cp_x(0, 0);
    cp_x(32, 1);
    store_w(0);
    load_w(32);
    cp_wait1();              // X0 arrived
    __syncthreads();         // X0 + W0 visible to all

    for (int c = 0; c < 4; c++) {
        const int bf = c & 1;
        if (c < 3) store_w(bf ^ 1);          // W_{c+1}
        if (c < 2) load_w((c + 2) * 32);     // W_{c+2} LDG

        const float* Xb = psm + bf * 2304;
        const float* Wb = Ws0 + bf * 4352;
#pragma unroll
        for (int s = 0; s < 4; s++) {
            int k0 = 8 * s + t;
            float aA0 = to_tf32(Xb[(mw + g)      * 36 + k0]);
            float aA1 = to_tf32(Xb[(mw + g + 8)  * 36 + k0]);
            float aA2 = to_tf32(Xb[(mw + g)      * 36 + k0 + 4]);
            float aA3 = to_tf32(Xb[(mw + g + 8)  * 36 + k0 + 4]);
            float aB0 = to_tf32(Xb[(mw + g + 16) * 36 + k0]);
            float aB1 = to_tf32(Xb[(mw + g + 24) * 36 + k0]);
            float aB2 = to_tf32(Xb[(mw + g + 16) * 36 + k0 + 4]);
            float aB3 = to_tf32(Xb[(mw + g + 24) * 36 + k0 + 4]);

            int p0 = g * 16 + w4;
            int sp0 = p0 ^ (((p0 >> 5) & 3) << 2);
            const float* wr0 = &Wb[(s * 8 + t) * 136 + sp0];
            const float* wr1 = wr0 + 4 * 136;
            float4 b0 = *(const float4*)wr0;
            float4 b1 = *(const float4*)wr1;
            float bb0[4] = {b0.x, b0.y, b0.z, b0.w};
            float bb1[4] = {b1.x, b1.y, b1.z, b1.w};
#pragma unroll
            for (int j = 0; j < 4; j++) {
                mma8(o[0][j], aA0, aA1, aA2, aA3, bb0[j], bb1[j]);
                mma8(o[1][j], aB0, aB1, aB2, aB3, bb0[j], bb1[j]);
            }
        }
        if (c < 3) cp_wait0();               // X_{c+1} arrived
        __syncthreads();                     // all consumed bf; W_{c+1} visible
        if (c < 2) cp_x((c + 2) * 32, bf);   // bf now free for X_{c+2}
    }

    const float qscale = 0.25503486f;   // 32^-0.5 * log2(e)
#pragma unroll
    for (int j = 0; j < 4; j++) {
        int col = nwq + 8 * j + 2 * t;
        if (MODE == 0) {
            float2 bv = *(const float2*)&bias[col];
#pragma unroll
            for (int mf = 0; mf < 2; mf++) {
                int r0 = rowb + mw + 16 * mf + g;
                *(float2*)&Y[(size_t)r0 * CC + col] =
                    make_float2(o[mf][j][0] + bv.x, o[mf][j][1] + bv.y);
                *(float2*)&Y[(size_t)(r0 + 8) * CC + col] =
                    make_float2(o[mf][j][2] + bv.x, o[mf][j][3] + bv.y);
            }
        } else {
            int h = col >> 5;
            int d0 = col & 31, d1 = d0 + 1;
            float bx = bias[col], by = bias[col + 1];
#pragma unroll
            for (int mf = 0; mf < 2; mf++) {
#pragma unroll
                for (int rh = 0; rh < 2; rh++) {
                    int row = rowb + mw + 16 * mf + g + 8 * rh;
                    float v0 = o[mf][j][2 * rh]     + bx;
                    float v1 = o[mf][j][2 * rh + 1] + by;
                    if (MODE == 2) { v0 *= qscale; v1 *= qscale; }
                    if (MODE == 4) {
                        int b = row / NKV, n = row % NKV;
                        int tile = n >> 6, rr = n & 63;
                        int off = ((rr & 7) >> 1) * 512 + 2 * (rr >> 3) + (rr & 1);
                        float* bp = &Y[(size_t)(b * HEADS + h) * VSTRIDE
                                       + tile * 2048 + off];
                        bp[d0 * 16] = to_tf32(v0);
                        bp[d1 * 16] = to_tf32(v1);
                    } else {
                        const int RPB = (MODE == 2) ? NQ : NKV;
                        int b = row / RPB, n = row % RPB;
                        int dp0 = (d0 & 3) * 8 + (d0 >> 2);
                        int dp1 = (d1 & 3) * 8 + (d1 >> 2);
                        float* bp = &Y[((size_t)(b * HEADS + h) * RPB + n) * DH];
                        bp[dp0] = to_tf32(v0);
                        bp[dp1] = to_tf32(v1);
                    }
                }
            }
        }
    }
}

// fused: q projection (tensor) + spatial-reduction conv
__global__ __launch_bounds__(256, 2) void qproj_conv_kernel(
    const float* __restrict__ x,
    const float* __restrict__ Wq, const float* __restrict__ bq, float* __restrict__ Q,
    const float* __restrict__ cw, const float* __restrict__ cb,
    const float* __restrict__ gamma, const float* __restrict__ beta,
    const float* __restrict__ mean, const float* __restrict__ var,
    float* __restrict__ xr)
{
    if (blockIdx.x < QPB64) {
        proj_mma_body64<2>(x, Wq, bq, Q, blockIdx.x * 64);
        return;
    }
    int t = (blockIdx.x - QPB64) * 256 + threadIdx.x;
    if (t >= BB * NKV * CC) return;
    int c = t & (CC - 1);
    int p = (t >> 7) % NKV;
    int b = t / (NKV * CC);
    int oy = p / 28, ox = p % 28;

    const float* xb = x + (size_t)b * NQ * CC;
    float s = 0.f;
#pragma unroll
    for (int i = 0; i < 2; i++)
#pragma unroll
        for (int j = 0; j < 2; j++)
            s += xb[(size_t)((2 * oy + i) * 56 + (2 * ox + j)) * CC + c] * cw[c * 4 + i * 2 + j];
    s += cb[c];
    float iv = gamma[c] * rsqrtf(var[c] + 1e-5f);
    xr[t] = s * iv + (beta[c] - mean[c] * iv);
}

// fused k+v projections (tensor mma)
__global__ __launch_bounds__(256, 2) void kvproj_kernel(
    const float* __restrict__ X,
    const float* __restrict__ Wk, const float* __restrict__ bk, float* __restrict__ K,
    const float* __restrict__ Wv, const float* __restrict__ bv, float* __restrict__ V)
{
    if (blockIdx.x < KVB64)
        proj_mma_body64<1>(X, Wk, bk, K, blockIdx.x * 64);
    else
        proj_mma_body64<4>(X, Wv, bv, V, (blockIdx.x - KVB64) * 64);
}

// output projection (tensor mma)
__global__ __launch_bounds__(256, 2) void oproj_kernel(
    const float* __restrict__ X, const float* __restrict__ W,
    const float* __restrict__ bias, float* __restrict__ Y)
{
    proj_mma_body64<0>(X, W, bias, Y, blockIdx.x * 64);
}

// empty probe: shifts the ncu capture slot so attention gets profiled
__global__ void probe_kernel() {}

// ---------------- mma attention: 8 warps x 16 queries, 256 threads --------
// dynamic smem layout (floats):
//   [0, 4608)        K double buffer (2 x 64 x 36)
//   [4608, 8736)     V double buffer (2 x 4 x 516)
//   [8736, 17952)    bias double buffer (2 x 128 x 36), half-tile (32 kv) each
#define VS_F    4608
#define BS_F    8736
#define SMEM_ATTN_F   17952
#define SMEM_ATTN_B   (SMEM_ATTN_F * 4)

template<int NC>
__device__ __forceinline__ void half_body(
    const float* __restrict__ Ksm, const float* __restrict__ Vsm,
    const float* __restrict__ Bsm,
    const float (&qreg)[2][8], float (&o)[4][4], float (&sums)[2],
    int c8base, int g, int t, int w)
{
    const float L2E = 1.4426950408889634f;
#pragma unroll
    for (int cc = 0; cc < NC; cc++) {
        const int c8 = c8base + cc;
        float2 cur[2];
#pragma unroll
        for (int rr = 0; rr < 2; rr++)
            cur[rr] = *(const float2*)(Bsm + (16 * w + 8 * rr + g) * 36 + 8 * cc + 2 * t);
        const float* kp = Ksm + (8 * c8 + g) * 36 + t * 8;
        float4 k0 = *(const float4*)kp;
        float4 k1 = *(const float4*)(kp + 4);
        float kb[8] = {k0.x, k0.y, k0.z, k0.w, k1.x, k1.y, k1.z, k1.w};
        float c0[4] = {0.f, 0.f, 0.f, 0.f};
#pragma unroll
        for (int s = 0; s < 4; s++)
            mma8(c0, qreg[0][2*s], qreg[1][2*s], qreg[0][2*s+1], qreg[1][2*s+1],
                 kb[2*s], kb[2*s+1]);
        float p00 = to_tf32(ex2(fmaf(cur[0].x, L2E, c0[0])));  // row g,   kv 2t
        float p02 = to_tf32(ex2(fmaf(cur[0].y, L2E, c0[1])));  // row g,   kv 2t+1
        float p10 = to_tf32(ex2(fmaf(cur[1].x, L2E, c0[2])));  // row g+8, kv 2t
        float p12 = to_tf32(ex2(fmaf(cur[1].y, L2E, c0[3])));
        sums[0] += p00 + p02;
        sums[1] += p10 + p12;
        const int posw = (c8 & 1) << 1;
        const int rh   = c8 >> 1;
#pragma unroll
        for (int nf = 0; nf < 4; nf++) {
            int d  = 8 * nf + g;
            int cv = ((d << 2) + rh) ^ ((d >> 1) & 3);
            float2 bv = *(const float2*)(Vsm + t * 516 + 4 * cv + posw);
            mma8(o[nf], p00, p10, p02, p12, bv.x, bv.y);
        }
    }
}

__global__ __launch_bounds__(256, 2) void attn_mma_kernel(
    const float* __restrict__ q, const float* __restrict__ k, const float* __restrict__ v,
    const float* __restrict__ relpos, float* __restrict__ out)
{
    extern __shared__ __align__(16) float dsm[];

    const int b   = blockIdx.z;
    const int h   = blockIdx.y;
    const int qt  = blockIdx.x;
    const int tid = threadIdx.x;
    const int lane = tid & 31, w = tid >> 5;   // w: 0..7
    const int g = lane >> 2, t = lane & 3;
    const int q0 = qt * 128;

    const float* qb = q + (size_t)(b * HEADS + h) * NQ * DH;
    const float* kb = k + (size_t)(b * HEADS + h) * NKV * DH;
    const float* vb = v + (size_t)(b * HEADS + h) * VSTRIDE;
    const float* rpb = relpos + (size_t)h * NQ * NKV;

    float qreg[2][8];
    int qraw[2];
#pragma unroll
    for (int rr = 0; rr < 2; rr++) {
        int qg = q0 + 16 * w + g + 8 * rr;
        qraw[rr] = qg;
        if (qg >= NQ) qg = NQ - 1;
        const float* qp = qb + (size_t)qg * DH + t * 8;
        float4 x0 = *(const float4*)qp;
        float4 x1 = *(const float4*)(qp + 4);
        qreg[rr][0] = x0.x; qreg[rr][1] = x0.y; qreg[rr][2] = x0.z; qreg[rr][3] = x0.w;
        qreg[rr][4] = x1.x; qreg[rr][5] = x1.y; qreg[rr][6] = x1.z; qreg[rr][7] = x1.w;
    }

    float o[4][4];
#pragma unroll
    for (int j = 0; j < 4; j++)
#pragma unroll
        for (int c = 0; c < 4; c++) o[j][c] = 0.f;
    float sums[2] = {0.f, 0.f};

    const unsigned kd_base = smem_u32(dsm);
    const unsigned vd_base = smem_u32(dsm + VS_F);
    const unsigned bd_base = smem_u32(dsm + BS_F);

    // coalesced bias stage: 128 rows x 32 kv into [128][36]; clamped addrs
    auto stage_bias = [&](unsigned bdst, int kcol) {
#pragma unroll
        for (int i = 0; i < 4; i++) {
            int G = tid + i * 256;
            int r = G >> 3, c = G & 7;
            int row = q0 + r; row = (row < NQ) ? row : (NQ - 1);
            int col = kcol + c * 4; col = (col <= NKV - 4) ? col : (NKV - 4);
            cp16(bdst + r * 144 + c * 16, rpb + (size_t)row * NKV + col);
        }
    };

    // prologue: KV tile 0 + bias half0
    {
#pragma unroll
        for (int i = 0; i < 4; i++) {
            int idx = tid + i * 256;
            if (idx < 512) {
                int r = idx >> 3, c = idx & 7;
                cp16(kd_base + r * 144 + c * 16, kb + idx * 4);
            } else {
                int j = idx - 512;
                int dst = (j >> 7) * 129 + ((j & 127) ^ ((j >> 3) & 3));
                cp16(vd_base + dst * 16, vb + j * 4);
            }
        }
    }
    cp_commit();
    stage_bias(bd_base, 0);
    cp_commit();

    for (int tt = 0; tt < 13; tt++) {
        const int buf = tt & 1;
        cp_wait0();
        __syncthreads();

        const float* Ksm = dsm + buf * 2304;
        const float* Vsm = dsm + VS_F + buf * 2064;
        const float* BsA = dsm + BS_F;
        const float* BsB = dsm + BS_F + 4608;

        if (tt < NFULL) {
            stage_bias(bd_base + 4608 * 4, tt * TN + 32);
            cp_commit();
            {
                const int nb = buf ^ 1;
                const unsigned kd = kd_base + nb * 9216;
                const unsigned vd = vd_base + nb * 8256;
                const float* kg = kb + (size_t)(tt + 1) * 2048;
                const float* vg = vb + (size_t)(tt + 1) * 2048;
                if (tt + 1 < NFULL) {
#pragma unroll
                    for (int i = 0; i < 4; i++) {
                        int idx = tid + i * 256;
                        if (idx < 512) {
                            int r = idx >> 3, c = idx & 7;
                            cp16(kd + r * 144 + c * 16, kg + idx * 4);
                        } else {
                            int j = idx - 512;
                            int dst = (j >> 7) * 129 + ((j & 127) ^ ((j >> 3) & 3));
                            cp16(vd + dst * 16, vg + j * 4);
                        }
                    }
                } else {
                    // tail tile: 16 kv rows -> 128 K-chunks + 128 V-chunks
                    int idx = tid;
                    if (idx < 128) {
                        int r = idx >> 3, c = idx & 7;
                        cp16(kd + r * 144 + c * 16, kg + idx * 4);
                    } else {
                        int j = idx - 128;
                        int grp = j >> 5, d = j & 31;
                        int dst = grp * 129 + ((d << 2) ^ ((d >> 1) & 3));
                        cp16(vd + dst * 16, vg + grp * 512 + d * 16);
                    }
                }
            }
            cp_commit();

            half_body<4>(Ksm, Vsm, BsA, qreg, o, sums, 0, g, t, w);

            cp_wait1();
            __syncthreads();

            stage_bias(bd_base, (tt + 1) * TN);
            cp_commit();

            half_body<4>(Ksm, Vsm, BsB, qreg, o, sums, 4, g, t, w);
        } else {
            half_body<2>(Ksm, Vsm, BsA, qreg, o, sums, 0, g, t, w);
        }
    }

    float inv[2];
#pragma unroll
    for (int rr = 0; rr < 2; rr++) {
        float s = sums[rr];
        s += __shfl_xor_sync(0xffffffffu, s, 1);
        s += __shfl_xor_sync(0xffffffffu, s, 2);
        inv[rr] = 1.f / s;
    }
#pragma unroll
    for (int rh = 0; rh < 2; rh++) {
        int qg = qraw[rh];
        if (qg >= NQ) continue;
        float* op = out + ((size_t)(b * NQ + qg)) * CC + h * 32 + 2 * t;
#pragma unroll
        for (int nf = 0; nf < 4; nf++) {
            float2 val = make_float2(o[nf][2 * rh] * inv[rh],
                                     o[nf][2 * rh + 1] * inv[rh]);
            *(float2*)(op + 8 * nf) = val;
        }
    }
}

// ---------------- launch ----------------
extern "C" void kernel_launch(void* const* d_in, const int* in_sizes, int n_in,
                              void* d_out, int out_size)
{
    const float* x      = (const float*)d_in[0];
    const float* relpos = (const float*)d_in[1];
    const float* Wq     = (const float*)d_in[2];
    const float* bq     = (const float*)d_in[3];
    const float* Wk     = (const float*)d_in[4];
    const float* bk     = (const float*)d_in[5];
    const float* Wv     = (const float*)d_in[6];
    const float* bv     = (const float*)d_in[7];
    const float* cw     = (const float*)d_in[8];
    const float* cb     = (const float*)d_in[9];
    const float* gamma  = (const float*)d_in[10];
    const float* beta   = (const float*)d_in[11];
    const float* mean   = (const float*)d_in[12];
    const float* var    = (const float*)d_in[13];
    const float* Wp     = (const float*)d_in[14];
    const float* bp     = (const float*)d_in[15];
    float* out = (float*)d_out;

    float *q, *k, *v, *xr, *ao;
    cudaGetSymbolAddress((void**)&q,  g_q);
    cudaGetSymbolAddress((void**)&k,  g_k);
    cudaGetSymbolAddress((void**)&v,  g_v);
    cudaGetSymbolAddress((void**)&xr, g_xr);
    cudaGetSymbolAddress((void**)&ao, g_ao);

    cudaFuncSetAttribute(attn_mma_kernel,
                         cudaFuncAttributeMaxDynamicSharedMemorySize, SMEM_ATTN_B);
    cudaFuncSetAttribute(qproj_conv_kernel,
                         cudaFuncAttributeMaxDynamicSharedMemorySize, PROJ_SMEM_B);
    cudaFuncSetAttribute(kvproj_kernel,
                         cudaFuncAttributeMaxDynamicSharedMemorySize, PROJ_SMEM_B);
    cudaFuncSetAttribute(oproj_kernel,
                         cudaFuncAttributeMaxDynamicSharedMemorySize, PROJ_SMEM_B);

    // 1) fused q projection (cp.async staged) + spatial-reduction conv
    int conv_blocks = (BB * NKV * CC + 255) / 256;
    qproj_conv_kernel<<<QPB64 + conv_blocks, 256, PROJ_SMEM_B>>>(
        x, Wq, bq, q, cw, cb, gamma, beta, mean, var, xr);
    // 2) fused k+v projections
    kvproj_kernel<<<2 * KVB64, 256, PROJ_SMEM_B>>>(xr, Wk, bk, k, Wv, bv, v);
    // probe: keeps ncu capture slot on the attention kernel
    probe_kernel<<<1, 32>>>();
    // 3) attention: 8 warps x 16 q, tf32 mma, smem-staged coalesced bias
    dim3 ag((NQ + 127) / 128, HEADS, BB);
    attn_mma_kernel<<<ag, 256, SMEM_ATTN_B>>>(q, k, v, relpos, ao);
    // 4) output projection
    oproj_kernel<<<QPB64, 256, PROJ_SMEM_B>>>(ao, Wp, bp, out);
}

// round 16
// speedup vs baseline: 1.1018x; 1.1018x over previous
#include <cuda_runtime.h>
#include <cstdint>

// ---------------- problem constants ----------------
#define BB      8
#define HEADS   4
#define NQ      3136
#define NKV     784
#define DH      32
#define CC      128
#define TN      64                 // kv tile (12 full tiles + tail of 16)
#define NFULL   12
#define VSTRIDE 26624              // 13 tiles * 2048 floats per (b,h)
#define QPB64   ((BB * NQ) / 64)   // 392
#define KVB64   ((BB * NKV) / 64)  // 98

typedef unsigned long long u64;

// ---------------- scratch (device globals; no allocation) ----------------
__device__ float g_q [BB * HEADS * NQ  * DH];      // permuted d', tf32, scaled by 32^-.5*log2e
__device__ float g_k [BB * HEADS * NKV * DH];      // permuted d', tf32
__device__ float g_v [BB * HEADS * VSTRIDE];       // sigma-permuted Vp, tf32
__device__ float g_xr[BB * NKV * CC];
__device__ float g_ao[BB * NQ  * CC];

// ---------------- helpers ----------------
__device__ __forceinline__ float to_tf32(float x) {
    float r; asm("cvt.rna.tf32.f32 %0, %1;" : "=f"(r) : "f"(x)); return r;
}
__device__ __forceinline__ float ex2(float x) {
    float r; asm("ex2.approx.f32 %0, %1;" : "=f"(r) : "f"(x)); return r;
}
__device__ __forceinline__ unsigned smem_u32(const void* p) {
    return (unsigned)__cvta_generic_to_shared(p);
}
__device__ __forceinline__ void cp16(unsigned dst, const void* src) {
    asm volatile("cp.async.cg.shared.global [%0], [%1], 16;\n" :: "r"(dst), "l"(src));
}
__device__ __forceinline__ void cp_commit() {
    asm volatile("cp.async.commit_group;\n" ::: "memory");
}
__device__ __forceinline__ void cp_wait0() {
    asm volatile("cp.async.wait_group 0;\n" ::: "memory");
}
__device__ __forceinline__ void cp_wait1() {
    asm volatile("cp.async.wait_group 1;\n" ::: "memory");
}

// mma.sync m16n8k8 tf32 (base PTX, sm_80+)
__device__ __forceinline__ void mma8(float c[4], float a0, float a1, float a2, float a3,
                                     float b0, float b1) {
    asm volatile(
        "mma.sync.aligned.m16n8k8.row.col.f32.tf32.tf32.f32 "
        "{%0,%1,%2,%3}, {%4,%5,%6,%7}, {%8,%9}, {%0,%1,%2,%3};"
        : "+f"(c[0]), "+f"(c[1]), "+f"(c[2]), "+f"(c[3])
        : "r"(__float_as_uint(a0)), "r"(__float_as_uint(a1)),
          "r"(__float_as_uint(a2)), "r"(__float_as_uint(a3)),
          "r"(__float_as_uint(b0)), "r"(__float_as_uint(b1)));
}

// ---------------- tensor-core projection: Y = X(64x128 tile) @ W + b ------
// CTA = 64 rows x 128 cols, 8 warps (2m x 4n). K chunks of 32.
// X staged by cp.async (coalesced) into raw-fp32 [64][36] buffers; A-scalars
// get cvt.rna at consume time. W register-staged (perm + XOR swizzle, tf32).
// One barrier per chunk.
// dynamic smem: Xs 2*2304 floats @0, Ws 2*4352 floats @4608. 53248 B.
#define PROJ_SMEM_B 53248
template<int MODE>
__device__ __forceinline__ void proj_mma_body64(
    const float* __restrict__ X, const float* __restrict__ W,
    const float* __restrict__ bias, float* __restrict__ Y, int rowb)
{
    extern __shared__ __align__(16) float psm[];
    float* Ws0 = psm + 4608;

    const int tid  = threadIdx.x;
    const int lane = tid & 31, w = tid >> 5;
    const int g = lane >> 2, t = lane & 3;
    const int mw  = (w & 1) * 32;
    const int nwq = (w >> 1) * 32;
    const int w4  = (w >> 1) * 4;
    const unsigned xs_base = smem_u32(psm);

    float o[2][4][4];
#pragma unroll
    for (int mf = 0; mf < 2; mf++)
#pragma unroll
        for (int j = 0; j < 4; j++)
#pragma unroll
            for (int c = 0; c < 4; c++) o[mf][j][c] = 0.f;

    float4 wa[4];
    auto cp_x = [&](int kc, int bf) {
#pragma unroll
        for (int i = 0; i < 2; i++) {
            int idx = tid + i * 256;
            int r = idx >> 3, c = idx & 7;
            cp16(xs_base + bf * 9216 + r * 144 + c * 16,
                 &X[(size_t)(rowb + r) * CC + kc + 4 * c]);
        }
        cp_commit();
    };
    auto load_w = [&](int kc) {
#pragma unroll
        for (int i = 0; i < 4; i++) {
            int vv = tid + i * 256;
            int kk = vv >> 5, ng = vv & 31;
            wa[i] = *(const float4*)&W[(size_t)(kc + kk) * CC + ng * 4];
        }
    };
    auto store_w = [&](int bf) {
#pragma unroll
        for (int i = 0; i < 4; i++) {
            int vv = tid + i * 256;
            int kk = vv >> 5, n0 = (vv & 31) * 4;
            float vals[4] = {to_tf32(wa[i].x), to_tf32(wa[i].y),
                             to_tf32(wa[i].z), to_tf32(wa[i].w)};
#pragma unroll
            for (int c2 = 0; c2 < 4; c2++) {
                int n = n0 + c2;
                int p = (n & 7) * 16 + (n >> 3);
                int sp = p ^ (((p >> 5) & 3) << 2);
                Ws0[bf * 4352 + kk * 136 + sp] = vals[c2];
            }
        }
    };

    // prologue: X0, X1 via cp.async; W0 staged; W1 in regs
    load_w(0);
    cp_x(0, 0);
    cp_x(32, 1);
    store_w(0);
    load_w(32);
    cp_wait1();              // X0 arrived
    __syncthreads();         // X0 + W0 visible to all

    for (int c = 0; c < 4; c++) {
        const int bf = c & 1;
        if (c < 3) store_w(bf ^ 1);          // W_{c+1}
        if (c < 2) load_w((c + 2) * 32);     // W_{c+2} LDG

        const float* Xb = psm + bf * 2304;
        const float* Wb = Ws0 + bf * 4352;
#pragma unroll
        for (int s = 0; s < 4; s++) {
            int k0 = 8 * s + t;
            float aA0 = to_tf32(Xb[(mw + g)      * 36 + k0]);
            float aA1 = to_tf32(Xb[(mw + g + 8)  * 36 + k0]);
            float aA2 = to_tf32(Xb[(mw + g)      * 36 + k0 + 4]);
            float aA3 = to_tf32(Xb[(mw + g + 8)  * 36 + k0 + 4]);
            float aB0 = to_tf32(Xb[(mw + g + 16) * 36 + k0]);
            float aB1 = to_tf32(Xb[(mw + g + 24) * 36 + k0]);
            float aB2 = to_tf32(Xb[(mw + g + 16) * 36 + k0 + 4]);
            float aB3 = to_tf32(Xb[(mw + g + 24) * 36 + k0 + 4]);

            int p0 = g * 16 + w4;
            int sp0 = p0 ^ (((p0 >> 5) & 3) << 2);
            const float* wr0 = &Wb[(s * 8 + t) * 136 + sp0];
            const float* wr1 = wr0 + 4 * 136;
            float4 b0 = *(const float4*)wr0;
            float4 b1 = *(const float4*)wr1;
            float bb0[4] = {b0.x, b0.y, b0.z, b0.w};
            float bb1[4] = {b1.x, b1.y, b1.z, b1.w};
#pragma unroll
            for (int j = 0; j < 4; j++) {
                mma8(o[0][j], aA0, aA1, aA2, aA3, bb0[j], bb1[j]);
                mma8(o[1][j], aB0, aB1, aB2, aB3, bb0[j], bb1[j]);
            }
        }
        if (c < 3) cp_wait0();               // X_{c+1} arrived
        __syncthreads();                     // all consumed bf; W_{c+1} visible
        if (c < 2) cp_x((c + 2) * 32, bf);   // bf now free for X_{c+2}
    }

    const float qscale = 0.25503486f;   // 32^-0.5 * log2(e)
#pragma unroll
    for (int j = 0; j < 4; j++) {
        int col = nwq + 8 * j + 2 * t;
        if (MODE == 0) {
            float2 bv = *(const float2*)&bias[col];
#pragma unroll
            for (int mf = 0; mf < 2; mf++) {
                int r0 = rowb + mw + 16 * mf + g;
                *(float2*)&Y[(size_t)r0 * CC + col] =
                    make_float2(o[mf][j][0] + bv.x, o[mf][j][1] + bv.y);
                *(float2*)&Y[(size_t)(r0 + 8) * CC + col] =
                    make_float2(o[mf][j][2] + bv.x, o[mf][j][3] + bv.y);
            }
        } else {
            int h = col >> 5;
            int d0 = col & 31, d1 = d0 + 1;
            float bx = bias[col], by = bias[col + 1];
#pragma unroll
            for (int mf = 0; mf < 2; mf++) {
#pragma unroll
                for (int rh = 0; rh < 2; rh++) {
                    int row = rowb + mw + 16 * mf + g + 8 * rh;
                    float v0 = o[mf][j][2 * rh]     + bx;
                    float v1 = o[mf][j][2 * rh + 1] + by;
                    if (MODE == 2) { v0 *= qscale; v1 *= qscale; }
                    if (MODE == 4) {
                        int b = row / NKV, n = row % NKV;
                        int tile = n >> 6, rr = n & 63;
                        int off = ((rr & 7) >> 1) * 512 + 2 * (rr >> 3) + (rr & 1);
                        float* bp = &Y[(size_t)(b * HEADS + h) * VSTRIDE
                                       + tile * 2048 + off];
                        bp[d0 * 16] = to_tf32(v0);
                        bp[d1 * 16] = to_tf32(v1);
                    } else {
                        const int RPB = (MODE == 2) ? NQ : NKV;
                        int b = row / RPB, n = row % RPB;
                        int dp0 = (d0 & 3) * 8 + (d0 >> 2);
                        int dp1 = (d1 & 3) * 8 + (d1 >> 2);
                        float* bp = &Y[((size_t)(b * HEADS + h) * RPB + n) * DH];
                        bp[dp0] = to_tf32(v0);
                        bp[dp1] = to_tf32(v1);
                    }
                }
            }
        }
    }
}

// fused: q projection (tensor) + spatial-reduction conv
__global__ __launch_bounds__(256, 2) void qproj_conv_kernel(
    const float* __restrict__ x,
    const float* __restrict__ Wq, const float* __restrict__ bq, float* __restrict__ Q,
    const float* __restrict__ cw, const float* __restrict__ cb,
    const float* __restrict__ gamma, const float* __restrict__ beta,
    const float* __restrict__ mean, const float* __restrict__ var,
    float* __restrict__ xr)
{
    if (blockIdx.x < QPB64) {
        proj_mma_body64<2>(x, Wq, bq, Q, blockIdx.x * 64);
        return;
    }
    int t = (blockIdx.x - QPB64) * 256 + threadIdx.x;
    if (t >= BB * NKV * CC) return;
    int c = t & (CC - 1);
    int p = (t >> 7) % NKV;
    int b = t / (NKV * CC);
    int oy = p / 28, ox = p % 28;

    const float* xb = x + (size_t)b * NQ * CC;
    float s = 0.f;
#pragma unroll
    for (int i = 0; i < 2; i++)
#pragma unroll
        for (int j = 0; j < 2; j++)
            s += xb[(size_t)((2 * oy + i) * 56 + (2 * ox + j)) * CC + c] * cw[c * 4 + i * 2 + j];
    s += cb[c];
    float iv = gamma[c] * rsqrtf(var[c] + 1e-5f);
    xr[t] = s * iv + (beta[c] - mean[c] * iv);
}

// fused k+v projections (tensor mma)
__global__ __launch_bounds__(256, 2) void kvproj_kernel(
    const float* __restrict__ X,
    const float* __restrict__ Wk, const float* __restrict__ bk, float* __restrict__ K,
    const float* __restrict__ Wv, const float* __restrict__ bv, float* __restrict__ V)
{
    if (blockIdx.x < KVB64)
        proj_mma_body64<1>(X, Wk, bk, K, blockIdx.x * 64);
    else
        proj_mma_body64<4>(X, Wv, bv, V, (blockIdx.x - KVB64) * 64);
}

// output projection (tensor mma)
__global__ __launch_bounds__(256, 2) void oproj_kernel(
    const float* __restrict__ X, const float* __restrict__ W,
    const float* __restrict__ bias, float* __restrict__ Y)
{
    proj_mma_body64<0>(X, W, bias, Y, blockIdx.x * 64);
}

// empty probe: shifts the ncu capture slot so attention gets profiled
__global__ void probe_kernel() {}

// ---------------- mma attention: 4 warps x 32 queries, 128 threads --------
// (round-14 winner layout: max K/V/bias reuse per warp)
// dynamic smem layout (floats):
//   [0, 4608)        K double buffer (2 x 64 x 36)
//   [4608, 8736)     V double buffer (2 x 4 x 516)
//   [8736, 17952)    bias double buffer (2 x 128 x 36), half-tile (32 kv) each
#define VS_F    4608
#define BS_F    8736
#define SMEM_ATTN_F   17952
#define SMEM_ATTN_B   (SMEM_ATTN_F * 4)

template<int NC>
__device__ __forceinline__ void half_body(
    const float* __restrict__ Ksm, const float* __restrict__ Vsm,
    const float* __restrict__ Bsm,
    const float (&qreg)[4][8], float (&o)[2][4][4], float (&sums)[4],
    int c8base, int g, int t, int w)
{
    const float L2E = 1.4426950408889634f;
#pragma unroll
    for (int cc = 0; cc < NC; cc++) {
        const int c8 = c8base + cc;
        float2 cur[4];
#pragma unroll
        for (int rr = 0; rr < 4; rr++)
            cur[rr] = *(const float2*)(Bsm + (32 * w + 8 * rr + g) * 36 + 8 * cc + 2 * t);
        const float* kp = Ksm + (8 * c8 + g) * 36 + t * 8;
        float4 k0 = *(const float4*)kp;
        float4 k1 = *(const float4*)(kp + 4);
        float kb[8] = {k0.x, k0.y, k0.z, k0.w, k1.x, k1.y, k1.z, k1.w};
        float c0[4] = {0.f, 0.f, 0.f, 0.f};
        float c1[4] = {0.f, 0.f, 0.f, 0.f};
#pragma unroll
        for (int s = 0; s < 4; s++) {
            mma8(c0, qreg[0][2*s], qreg[1][2*s], qreg[0][2*s+1], qreg[1][2*s+1],
                 kb[2*s], kb[2*s+1]);
            mma8(c1, qreg[2][2*s], qreg[3][2*s], qreg[2][2*s+1], qreg[3][2*s+1],
                 kb[2*s], kb[2*s+1]);
        }
        float p00 = to_tf32(ex2(fmaf(cur[0].x, L2E, c0[0])));
        float p02 = to_tf32(ex2(fmaf(cur[0].y, L2E, c0[1])));
        float p10 = to_tf32(ex2(fmaf(cur[1].x, L2E, c0[2])));
        float p12 = to_tf32(ex2(fmaf(cur[1].y, L2E, c0[3])));
        float p20 = to_tf32(ex2(fmaf(cur[2].x, L2E, c1[0])));
        float p22 = to_tf32(ex2(fmaf(cur[2].y, L2E, c1[1])));
        float p30 = to_tf32(ex2(fmaf(cur[3].x, L2E, c1[2])));
        float p32 = to_tf32(ex2(fmaf(cur[3].y, L2E, c1[3])));
        sums[0] += p00 + p02; sums[1] += p10 + p12;
        sums[2] += p20 + p22; sums[3] += p30 + p32;
        const int posw = (c8 & 1) << 1;
        const int rh   = c8 >> 1;
#pragma unroll
        for (int nf = 0; nf < 4; nf++) {
            int d  = 8 * nf + g;
            int cv = ((d << 2) + rh) ^ ((d >> 1) & 3);
            float2 bv = *(const float2*)(Vsm + t * 516 + 4 * cv + posw);
            mma8(o[0][nf], p00, p10, p02, p12, bv.x, bv.y);
            mma8(o[1][nf], p20, p30, p22, p32, bv.x, bv.y);
        }
    }
}

__global__ __launch_bounds__(128, 3) void attn_mma_kernel(
    const float* __restrict__ q, const float* __restrict__ k, const float* __restrict__ v,
    const float* __restrict__ relpos, float* __restrict__ out)
{
    extern __shared__ __align__(16) float dsm[];

    const int b   = blockIdx.z;
    const int h   = blockIdx.y;
    const int qt  = blockIdx.x;
    const int tid = threadIdx.x;
    const int lane = tid & 31, w = tid >> 5;
    const int g = lane >> 2, t = lane & 3;
    const int q0 = qt * 128;

    const float* qb = q + (size_t)(b * HEADS + h) * NQ * DH;
    const float* kb = k + (size_t)(b * HEADS + h) * NKV * DH;
    const float* vb = v + (size_t)(b * HEADS + h) * VSTRIDE;
    const float* rpb = relpos + (size_t)h * NQ * NKV;

    float qreg[4][8];
    int qraw[4];
#pragma unroll
    for (int rr = 0; rr < 4; rr++) {
        int qg = q0 + 32 * w + g + 8 * rr;
        qraw[rr] = qg;
        if (qg >= NQ) qg = NQ - 1;
        const float* qp = qb + (size_t)qg * DH + t * 8;
        float4 x0 = *(const float4*)qp;
        float4 x1 = *(const float4*)(qp + 4);
        qreg[rr][0] = x0.x; qreg[rr][1] = x0.y; qreg[rr][2] = x0.z; qreg[rr][3] = x0.w;
        qreg[rr][4] = x1.x; qreg[rr][5] = x1.y; qreg[rr][6] = x1.z; qreg[rr][7] = x1.w;
    }

    float o[2][4][4];
#pragma unroll
    for (int i = 0; i < 2; i++)
#pragma unroll
        for (int j = 0; j < 4; j++)
#pragma unroll
            for (int c = 0; c < 4; c++) o[i][j][c] = 0.f;
    float sums[4] = {0.f, 0.f, 0.f, 0.f};

    const unsigned kd_base = smem_u32(dsm);
    const unsigned vd_base = smem_u32(dsm + VS_F);
    const unsigned bd_base = smem_u32(dsm + BS_F);

    auto stage_bias = [&](unsigned bdst, int kcol) {
#pragma unroll
        for (int i = 0; i < 8; i++) {
            int G = tid + i * 128;
            int r = G >> 3, c = G & 7;
            int row = q0 + r; row = (row < NQ) ? row : (NQ - 1);
            int col = kcol + c * 4; col = (col <= NKV - 4) ? col : (NKV - 4);
            cp16(bdst + r * 144 + c * 16, rpb + (size_t)row * NKV + col);
        }
    };

    {
#pragma unroll
        for (int i = 0; i < 8; i++) {
            int idx = tid + i * 128;
            if (idx < 512) {
                int r = idx >> 3, c = idx & 7;
                cp16(kd_base + r * 144 + c * 16, kb + idx * 4);
            } else {
                int j = idx - 512;
                int dst = (j >> 7) * 129 + ((j & 127) ^ ((j >> 3) & 3));
                cp16(vd_base + dst * 16, vb + j * 4);
            }
        }
    }
    cp_commit();
    stage_bias(bd_base, 0);
    cp_commit();

    for (int tt = 0; tt < 13; tt++) {
        const int buf = tt & 1;
        cp_wait0();
        __syncthreads();

        const float* Ksm = dsm + buf * 2304;
        const float* Vsm = dsm + VS_F + buf * 2064;
        const float* BsA = dsm + BS_F;
        const float* BsB = dsm + BS_F + 4608;

        if (tt < NFULL) {
            stage_bias(bd_base + 4608 * 4, tt * TN + 32);
            cp_commit();
            {
                const int nb = buf ^ 1;
                const unsigned kd = kd_base + nb * 9216;
                const unsigned vd = vd_base + nb * 8256;
                const float* kg = kb + (size_t)(tt + 1) * 2048;
                const float* vg = vb + (size_t)(tt + 1) * 2048;
                if (tt + 1 < NFULL) {
#pragma unroll
                    for (int i = 0; i < 8; i++) {
                        int idx = tid + i * 128;
                        if (idx < 512) {
                            int r = idx >> 3, c = idx & 7;
                            cp16(kd + r * 144 + c * 16, kg + idx * 4);
                        } else {
                            int j = idx - 512;
                            int dst = (j >> 7) * 129 + ((j & 127) ^ ((j >> 3) & 3));
                            cp16(vd + dst * 16, vg + j * 4);
                        }
                    }
                } else {
#pragma unroll
                    for (int i = 0; i < 2; i++) {
                        int idx = tid + i * 128;
                        if (idx < 128) {
                            int r = idx >> 3, c = idx & 7;
                            cp16(kd + r * 144 + c * 16, kg + idx * 4);
                        } else {
                            int j = idx - 128;
                            int grp = j >> 5, d = j & 31;
                            int dst = grp * 129 + ((d << 2) ^ ((d >> 1) & 3));
                            cp16(vd + dst * 16, vg + grp * 512 + d * 16);
                        }
                    }
                }
            }
            cp_commit();

            half_body<4>(Ksm, Vsm, BsA, qreg, o, sums, 0, g, t, w);

            cp_wait1();
            __syncthreads();

            stage_bias(bd_base, (tt + 1) * TN);
            cp_commit();

            half_body<4>(Ksm, Vsm, BsB, qreg, o, sums, 4, g, t, w);
        } else {
            half_body<2>(Ksm, Vsm, BsA, qreg, o, sums, 0, g, t, w);
        }
    }

    float inv[4];
#pragma unroll
    for (int rr = 0; rr < 4; rr++) {
        float s = sums[rr];
        s += __shfl_xor_sync(0xffffffffu, s, 1);
        s += __shfl_xor_sync(0xffffffffu, s, 2);
        inv[rr] = 1.f / s;
    }
#pragma unroll
    for (int mf = 0; mf < 2; mf++) {
#pragma unroll
        for (int rh = 0; rh < 2; rh++) {
            int rr = 2 * mf + rh;
            int qg = qraw[rr];
            if (qg >= NQ) continue;
            float* op = out + ((size_t)(b * NQ + qg)) * CC + h * 32 + 2 * t;
#pragma unroll
            for (int nf = 0; nf < 4; nf++) {
                float2 val = make_float2(o[mf][nf][2 * rh] * inv[rr],
                                         o[mf][nf][2 * rh + 1] * inv[rr]);
                *(float2*)(op + 8 * nf) = val;
            }
        }
    }
}

// ---------------- launch ----------------
extern "C" void kernel_launch(void* const* d_in, const int* in_sizes, int n_in,
                              void* d_out, int out_size)
{
    const float* x      = (const float*)d_in[0];
    const float* relpos = (const float*)d_in[1];
    const float* Wq     = (const float*)d_in[2];
    const float* bq     = (const float*)d_in[3];
    const float* Wk     = (const float*)d_in[4];
    const float* bk     = (const float*)d_in[5];
    const float* Wv     = (const float*)d_in[6];
    const float* bv     = (const float*)d_in[7];
    const float* cw     = (const float*)d_in[8];
    const float* cb     = (const float*)d_in[9];
    const float* gamma  = (const float*)d_in[10];
    const float* beta   = (const float*)d_in[11];
    const float* mean   = (const float*)d_in[12];
    const float* var    = (const float*)d_in[13];
    const float* Wp     = (const float*)d_in[14];
    const float* bp     = (const float*)d_in[15];
    float* out = (float*)d_out;

    float *q, *k, *v, *xr, *ao;
    cudaGetSymbolAddress((void**)&q,  g_q);
    cudaGetSymbolAddress((void**)&k,  g_k);
    cudaGetSymbolAddress((void**)&v,  g_v);
    cudaGetSymbolAddress((void**)&xr, g_xr);
    cudaGetSymbolAddress((void**)&ao, g_ao);

    cudaFuncSetAttribute(attn_mma_kernel,
                         cudaFuncAttributeMaxDynamicSharedMemorySize, SMEM_ATTN_B);
    cudaFuncSetAttribute(qproj_conv_kernel,
                         cudaFuncAttributeMaxDynamicSharedMemorySize, PROJ_SMEM_B);
    cudaFuncSetAttribute(kvproj_kernel,
                         cudaFuncAttributeMaxDynamicSharedMemorySize, PROJ_SMEM_B);
    cudaFuncSetAttribute(oproj_kernel,
                         cudaFuncAttributeMaxDynamicSharedMemorySize, PROJ_SMEM_B);

    // 1) fused q projection (cp.async staged) + spatial-reduction conv
    int conv_blocks = (BB * NKV * CC + 255) / 256;
    qproj_conv_kernel<<<QPB64 + conv_blocks, 256, PROJ_SMEM_B>>>(
        x, Wq, bq, q, cw, cb, gamma, beta, mean, var, xr);
    // 2) fused k+v projections
    kvproj_kernel<<<2 * KVB64, 256, PROJ_SMEM_B>>>(xr, Wk, bk, k, Wv, bv, v);
    // probe: keeps ncu capture slot on the attention kernel
    probe_kernel<<<1, 32>>>();
    // 3) attention: 4 warps x 32 q (max reuse), tf32 mma, smem-staged bias
    dim3 ag((NQ + 127) / 128, HEADS, BB);
    attn_mma_kernel<<<ag, 128, SMEM_ATTN_B>>>(q, k, v, relpos, ao);
    // 4) output projection
    oproj_kernel<<<QPB64, 256, PROJ_SMEM_B>>>(ao, Wp, bp, out);
}

// round 17
// speedup vs baseline: 1.1049x; 1.0029x over previous
#include <cuda_runtime.h>
#include <cstdint>

// ---------------- problem constants ----------------
#define BB      8
#define HEADS   4
#define NQ      3136
#define NKV     784
#define DH      32
#define CC      128
#define TN      64                 // kv tile (12 full tiles + tail of 16)
#define NFULL   12
#define VSTRIDE 26624              // 13 tiles * 2048 floats per (b,h)
#define QPB64   ((BB * NQ) / 64)   // 392
#define KVB64   ((BB * NKV) / 64)  // 98

typedef unsigned long long u64;

// ---------------- scratch (device globals; no allocation) ----------------
__device__ float g_q [BB * HEADS * NQ  * DH];      // permuted d', tf32, scaled by 32^-.5*log2e
__device__ float g_k [BB * HEADS * NKV * DH];      // permuted d', tf32
__device__ float g_v [BB * HEADS * VSTRIDE];       // sigma-permuted Vp, tf32
__device__ float g_xr[BB * NKV * CC];
__device__ float g_ao[BB * NQ  * CC];

// ---------------- helpers ----------------
__device__ __forceinline__ float to_tf32(float x) {
    float r; asm("cvt.rna.tf32.f32 %0, %1;" : "=f"(r) : "f"(x)); return r;
}
__device__ __forceinline__ float ex2(float x) {
    float r; asm("ex2.approx.f32 %0, %1;" : "=f"(r) : "f"(x)); return r;
}
__device__ __forceinline__ unsigned smem_u32(const void* p) {
    return (unsigned)__cvta_generic_to_shared(p);
}
__device__ __forceinline__ void cp16(unsigned dst, const void* src) {
    asm volatile("cp.async.cg.shared.global [%0], [%1], 16;\n" :: "r"(dst), "l"(src));
}
__device__ __forceinline__ void cp_commit() {
    asm volatile("cp.async.commit_group;\n" ::: "memory");
}
__device__ __forceinline__ void cp_wait0() {
    asm volatile("cp.async.wait_group 0;\n" ::: "memory");
}
__device__ __forceinline__ void cp_wait1() {
    asm volatile("cp.async.wait_group 1;\n" ::: "memory");
}

// mma.sync m16n8k8 tf32 (base PTX, sm_80+)
__device__ __forceinline__ void mma8(float c[4], float a0, float a1, float a2, float a3,
                                     float b0, float b1) {
    asm volatile(
        "mma.sync.aligned.m16n8k8.row.col.f32.tf32.tf32.f32 "
        "{%0,%1,%2,%3}, {%4,%5,%6,%7}, {%8,%9}, {%0,%1,%2,%3};"
        : "+f"(c[0]), "+f"(c[1]), "+f"(c[2]), "+f"(c[3])
        : "r"(__float_as_uint(a0)), "r"(__float_as_uint(a1)),
          "r"(__float_as_uint(a2)), "r"(__float_as_uint(a3)),
          "r"(__float_as_uint(b0)), "r"(__float_as_uint(b1)));
}

// ---------------- tensor-core projection: Y = X(64x128 tile) @ W + b ------
// CTA = 64 rows x 128 cols, 8 warps (2m x 4n). K chunks of 32.
// X staged by cp.async (coalesced) into raw-fp32 [64][36] buffers; A-scalars
// get cvt.rna at consume time. W register-staged (perm + XOR swizzle, tf32).
// One barrier per chunk.
// dynamic smem: Xs 2*2304 floats @0, Ws 2*4352 floats @4608. 53248 B.
#define PROJ_SMEM_B 53248
template<int MODE>
__device__ __forceinline__ void proj_mma_body64(
    const float* __restrict__ X, const float* __restrict__ W,
    const float* __restrict__ bias, float* __restrict__ Y, int rowb)
{
    extern __shared__ __align__(16) float psm[];
    float* Ws0 = psm + 4608;

    const int tid  = threadIdx.x;
    const int lane = tid & 31, w = tid >> 5;
    const int g = lane >> 2, t = lane & 3;
    const int mw  = (w & 1) * 32;
    const int nwq = (w >> 1) * 32;
    const int w4  = (w >> 1) * 4;
    const unsigned xs_base = smem_u32(psm);

    float o[2][4][4];
#pragma unroll
    for (int mf = 0; mf < 2; mf++)
#pragma unroll
        for (int j = 0; j < 4; j++)
#pragma unroll
            for (int c = 0; c < 4; c++) o[mf][j][c] = 0.f;

    float4 wa[4];
    auto cp_x = [&](int kc, int bf) {
#pragma unroll
        for (int i = 0; i < 2; i++) {
            int idx = tid + i * 256;
            int r = idx >> 3, c = idx & 7;
            cp16(xs_base + bf * 9216 + r * 144 + c * 16,
                 &X[(size_t)(rowb + r) * CC + kc + 4 * c]);
        }
        cp_commit();
    };
    auto load_w = [&](int kc) {
#pragma unroll
        for (int i = 0; i < 4; i++) {
            int vv = tid + i * 256;
            int kk = vv >> 5, ng = vv & 31;
            wa[i] = *(const float4*)&W[(size_t)(kc + kk) * CC + ng * 4];
        }
    };
    auto store_w = [&](int bf) {
#pragma unroll
        for (int i = 0; i < 4; i++) {
            int vv = tid + i * 256;
            int kk = vv >> 5, n0 = (vv & 31) * 4;
            float vals[4] = {to_tf32(wa[i].x), to_tf32(wa[i].y),
                             to_tf32(wa[i].z), to_tf32(wa[i].w)};
#pragma unroll
            for (int c2 = 0; c2 < 4; c2++) {
                int n = n0 + c2;
                int p = (n & 7) * 16 + (n >> 3);
                int sp = p ^ (((p >> 5) & 3) << 2);
                Ws0[bf * 4352 + kk * 136 + sp] = vals[c2];
            }
        }
    };

    // prologue: X0, X1 via cp.async; W0 staged; W1 in regs
    load_w(0);
    cp_x(0, 0);
    cp_x(32, 1);
    store_w(0);
    load_w(32);
    cp_wait1();              // X0 arrived
    __syncthreads();         // X0 + W0 visible to all

    for (int c = 0; c < 4; c++) {
        const int bf = c & 1;
        if (c < 3) store_w(bf ^ 1);          // W_{c+1}
        if (c < 2) load_w((c + 2) * 32);     // W_{c+2} LDG

        const float* Xb = psm + bf * 2304;
        const float* Wb = Ws0 + bf * 4352;
#pragma unroll
        for (int s = 0; s < 4; s++) {
            int k0 = 8 * s + t;
            float aA0 = to_tf32(Xb[(mw + g)      * 36 + k0]);
            float aA1 = to_tf32(Xb[(mw + g + 8)  * 36 + k0]);
            float aA2 = to_tf32(Xb[(mw + g)      * 36 + k0 + 4]);
            float aA3 = to_tf32(Xb[(mw + g + 8)  * 36 + k0 + 4]);
            float aB0 = to_tf32(Xb[(mw + g + 16) * 36 + k0]);
            float aB1 = to_tf32(Xb[(mw + g + 24) * 36 + k0]);
            float aB2 = to_tf32(Xb[(mw + g + 16) * 36 + k0 + 4]);
            float aB3 = to_tf32(Xb[(mw + g + 24) * 36 + k0 + 4]);

            int p0 = g * 16 + w4;
            int sp0 = p0 ^ (((p0 >> 5) & 3) << 2);
            const float* wr0 = &Wb[(s * 8 + t) * 136 + sp0];
            const float* wr1 = wr0 + 4 * 136;
            float4 b0 = *(const float4*)wr0;
            float4 b1 = *(const float4*)wr1;
            float bb0[4] = {b0.x, b0.y, b0.z, b0.w};
            float bb1[4] = {b1.x, b1.y, b1.z, b1.w};
#pragma unroll
            for (int j = 0; j < 4; j++) {
                mma8(o[0][j], aA0, aA1, aA2, aA3, bb0[j], bb1[j]);
                mma8(o[1][j], aB0, aB1, aB2, aB3, bb0[j], bb1[j]);
            }
        }
        if (c < 3) cp_wait0();               // X_{c+1} arrived
        __syncthreads();                     // all consumed bf; W_{c+1} visible
        if (c < 2) cp_x((c + 2) * 32, bf);   // bf now free for X_{c+2}
    }

    const float qscale = 0.25503486f;   // 32^-0.5 * log2(e)
#pragma unroll
    for (int j = 0; j < 4; j++) {
        int col = nwq + 8 * j + 2 * t;
        if (MODE == 0) {
            float2 bv = *(const float2*)&bias[col];
#pragma unroll
            for (int mf = 0; mf < 2; mf++) {
                int r0 = rowb + mw + 16 * mf + g;
                *(float2*)&Y[(size_t)r0 * CC + col] =
                    make_float2(o[mf][j][0] + bv.x, o[mf][j][1] + bv.y);
                *(float2*)&Y[(size_t)(r0 + 8) * CC + col] =
                    make_float2(o[mf][j][2] + bv.x, o[mf][j][3] + bv.y);
            }
        } else {
            int h = col >> 5;
            int d0 = col & 31, d1 = d0 + 1;
            float bx = bias[col], by = bias[col + 1];
#pragma unroll
            for (int mf = 0; mf < 2; mf++) {
#pragma unroll
                for (int rh = 0; rh < 2; rh++) {
                    int row = rowb + mw + 16 * mf + g + 8 * rh;
                    float v0 = o[mf][j][2 * rh]     + bx;
                    float v1 = o[mf][j][2 * rh + 1] + by;
                    if (MODE == 2) { v0 *= qscale; v1 *= qscale; }
                    if (MODE == 4) {
                        int b = row / NKV, n = row % NKV;
                        int tile = n >> 6, rr = n & 63;
                        int off = ((rr & 7) >> 1) * 512 + 2 * (rr >> 3) + (rr & 1);
                        float* bp = &Y[(size_t)(b * HEADS + h) * VSTRIDE
                                       + tile * 2048 + off];
                        bp[d0 * 16] = to_tf32(v0);
                        bp[d1 * 16] = to_tf32(v1);
                    } else {
                        const int RPB = (MODE == 2) ? NQ : NKV;
                        int b = row / RPB, n = row % RPB;
                        int dp0 = (d0 & 3) * 8 + (d0 >> 2);
                        int dp1 = (d1 & 3) * 8 + (d1 >> 2);
                        float* bp = &Y[((size_t)(b * HEADS + h) * RPB + n) * DH];
                        bp[dp0] = to_tf32(v0);
                        bp[dp1] = to_tf32(v1);
                    }
                }
            }
        }
    }
}

// fused: q projection (tensor) + spatial-reduction conv
__global__ __launch_bounds__(256, 2) void qproj_conv_kernel(
    const float* __restrict__ x,
    const float* __restrict__ Wq, const float* __restrict__ bq, float* __restrict__ Q,
    const float* __restrict__ cw, const float* __restrict__ cb,
    const float* __restrict__ gamma, const float* __restrict__ beta,
    const float* __restrict__ mean, const float* __restrict__ var,
    float* __restrict__ xr)
{
    if (blockIdx.x < QPB64) {
        proj_mma_body64<2>(x, Wq, bq, Q, blockIdx.x * 64);
        return;
    }
    int t = (blockIdx.x - QPB64) * 256 + threadIdx.x;
    if (t >= BB * NKV * CC) return;
    int c = t & (CC - 1);
    int p = (t >> 7) % NKV;
    int b = t / (NKV * CC);
    int oy = p / 28, ox = p % 28;

    const float* xb = x + (size_t)b * NQ * CC;
    float s = 0.f;
#pragma unroll
    for (int i = 0; i < 2; i++)
#pragma unroll
        for (int j = 0; j < 2; j++)
            s += xb[(size_t)((2 * oy + i) * 56 + (2 * ox + j)) * CC + c] * cw[c * 4 + i * 2 + j];
    s += cb[c];
    float iv = gamma[c] * rsqrtf(var[c] + 1e-5f);
    xr[t] = s * iv + (beta[c] - mean[c] * iv);
}

// fused k+v projections (tensor mma)
__global__ __launch_bounds__(256, 2) void kvproj_kernel(
    const float* __restrict__ X,
    const float* __restrict__ Wk, const float* __restrict__ bk, float* __restrict__ K,
    const float* __restrict__ Wv, const float* __restrict__ bv, float* __restrict__ V)
{
    if (blockIdx.x < KVB64)
        proj_mma_body64<1>(X, Wk, bk, K, blockIdx.x * 64);
    else
        proj_mma_body64<4>(X, Wv, bv, V, (blockIdx.x - KVB64) * 64);
}

// output projection (tensor mma)
__global__ __launch_bounds__(256, 2) void oproj_kernel(
    const float* __restrict__ X, const float* __restrict__ W,
    const float* __restrict__ bias, float* __restrict__ Y)
{
    proj_mma_body64<0>(X, W, bias, Y, blockIdx.x * 64);
}

// empty probe: shifts the ncu capture slot so attention gets profiled
__global__ void probe_kernel() {}

// ---------------- mma attention: 4 warps x 32 queries, 128 threads --------
// dynamic smem layout (floats):
//   [0, 4608)        K double buffer (2 x 64 x 36)
//   [4608, 8736)     V double buffer (2 x 4 x 516)
//   [8736, 17952)    bias double buffer (2 x 128 x 36), half-tile (32 kv) each
#define VS_F    4608
#define BS_F    8736
#define SMEM_ATTN_F   17952
#define SMEM_ATTN_B   (SMEM_ATTN_F * 4)

// QK accumulators split into 2-deep chains (c*a: s=0,1; c*b: s=2,3) -> 4
// independent mma chains; bias/V addresses hoisted to base + immediates.
template<int NC>
__device__ __forceinline__ void half_body(
    const float* __restrict__ Ksm, const float* __restrict__ Vsm,
    const float* __restrict__ Bsm,
    const float (&qreg)[4][8], float (&o)[2][4][4], float (&sums)[4],
    int c8base, int g, int t, int w)
{
    const float L2E = 1.4426950408889634f;
    const float* Bp  = Bsm + (32 * w + g) * 36 + 2 * t;  // +288*rr, +8*cc
    const int    swz = (g >> 1) & 3;
    const float* Vp  = Vsm + t * 516;                    // +4*e +128*nf
#pragma unroll
    for (int cc = 0; cc < NC; cc++) {
        const int c8 = c8base + cc;
        float2 cur[4];
#pragma unroll
        for (int rr = 0; rr < 4; rr++)
            cur[rr] = *(const float2*)(Bp + rr * 288 + 8 * cc);

        const float* kp = Ksm + (8 * c8 + g) * 36 + t * 8;
        float4 k0 = *(const float4*)kp;
        float4 k1 = *(const float4*)(kp + 4);
        float kb[8] = {k0.x, k0.y, k0.z, k0.w, k1.x, k1.y, k1.z, k1.w};

        // ---- S chunk = Q @ K^T: 4 independent 2-deep chains ----
        float c0a[4] = {0.f, 0.f, 0.f, 0.f}, c0b[4] = {0.f, 0.f, 0.f, 0.f};
        float c1a[4] = {0.f, 0.f, 0.f, 0.f}, c1b[4] = {0.f, 0.f, 0.f, 0.f};
        mma8(c0a, qreg[0][0], qreg[1][0], qreg[0][1], qreg[1][1], kb[0], kb[1]);
        mma8(c1a, qreg[2][0], qreg[3][0], qreg[2][1], qreg[3][1], kb[0], kb[1]);
        mma8(c0b, qreg[0][4], qreg[1][4], qreg[0][5], qreg[1][5], kb[4], kb[5]);
        mma8(c1b, qreg[2][4], qreg[3][4], qreg[2][5], qreg[3][5], kb[4], kb[5]);
        mma8(c0a, qreg[0][2], qreg[1][2], qreg[0][3], qreg[1][3], kb[2], kb[3]);
        mma8(c1a, qreg[2][2], qreg[3][2], qreg[2][3], qreg[3][3], kb[2], kb[3]);
        mma8(c0b, qreg[0][6], qreg[1][6], qreg[0][7], qreg[1][7], kb[6], kb[7]);
        mma8(c1b, qreg[2][6], qreg[3][6], qreg[2][7], qreg[3][7], kb[6], kb[7]);

        // ---- exp2(S + bias) -> P (registers), accumulate sums ----
        float p00 = to_tf32(ex2(fmaf(cur[0].x, L2E, c0a[0] + c0b[0])));
        float p02 = to_tf32(ex2(fmaf(cur[0].y, L2E, c0a[1] + c0b[1])));
        float p10 = to_tf32(ex2(fmaf(cur[1].x, L2E, c0a[2] + c0b[2])));
        float p12 = to_tf32(ex2(fmaf(cur[1].y, L2E, c0a[3] + c0b[3])));
        float p20 = to_tf32(ex2(fmaf(cur[2].x, L2E, c1a[0] + c1b[0])));
        float p22 = to_tf32(ex2(fmaf(cur[2].y, L2E, c1a[1] + c1b[1])));
        float p30 = to_tf32(ex2(fmaf(cur[3].x, L2E, c1a[2] + c1b[2])));
        float p32 = to_tf32(ex2(fmaf(cur[3].y, L2E, c1a[3] + c1b[3])));
        sums[0] += p00 + p02; sums[1] += p10 + p12;
        sums[2] += p20 + p22; sums[3] += p30 + p32;

        // ---- O += P @ V (hoisted swizzle: addr = Vp + e4 + 128*nf) ----
        const int posw = (c8 & 1) << 1;
        const int rh   = c8 >> 1;
        const int e4   = 4 * (((g << 2) + rh) ^ swz) + posw;
        const float* vp = Vp + e4;
#pragma unroll
        for (int nf = 0; nf < 4; nf++) {
            float2 bv = *(const float2*)(vp + 128 * nf);
            mma8(o[0][nf], p00, p10, p02, p12, bv.x, bv.y);
            mma8(o[1][nf], p20, p30, p22, p32, bv.x, bv.y);
        }
    }
}

__global__ __launch_bounds__(128, 3) void attn_mma_kernel(
    const float* __restrict__ q, const float* __restrict__ k, const float* __restrict__ v,
    const float* __restrict__ relpos, float* __restrict__ out)
{
    extern __shared__ __align__(16) float dsm[];

    const int b   = blockIdx.z;
    const int h   = blockIdx.y;
    const int qt  = blockIdx.x;
    const int tid = threadIdx.x;
    const int lane = tid & 31, w = tid >> 5;
    const int g = lane >> 2, t = lane & 3;
    const int q0 = qt * 128;

    const float* qb = q + (size_t)(b * HEADS + h) * NQ * DH;
    const float* kb = k + (size_t)(b * HEADS + h) * NKV * DH;
    const float* vb = v + (size_t)(b * HEADS + h) * VSTRIDE;
    const float* rpb = relpos + (size_t)h * NQ * NKV;

    float qreg[4][8];
    int qraw[4];
#pragma unroll
    for (int rr = 0; rr < 4; rr++) {
        int qg = q0 + 32 * w + g + 8 * rr;
        qraw[rr] = qg;
        if (qg >= NQ) qg = NQ - 1;
        const float* qp = qb + (size_t)qg * DH + t * 8;
        float4 x0 = *(const float4*)qp;
        float4 x1 = *(const float4*)(qp + 4);
        qreg[rr][0] = x0.x; qreg[rr][1] = x0.y; qreg[rr][2] = x0.z; qreg[rr][3] = x0.w;
        qreg[rr][4] = x1.x; qreg[rr][5] = x1.y; qreg[rr][6] = x1.z; qreg[rr][7] = x1.w;
    }

    float o[2][4][4];
#pragma unroll
    for (int i = 0; i < 2; i++)
#pragma unroll
        for (int j = 0; j < 4; j++)
#pragma unroll
            for (int c = 0; c < 4; c++) o[i][j][c] = 0.f;
    float sums[4] = {0.f, 0.f, 0.f, 0.f};

    const unsigned kd_base = smem_u32(dsm);
    const unsigned vd_base = smem_u32(dsm + VS_F);
    const unsigned bd_base = smem_u32(dsm + BS_F);

    auto stage_bias = [&](unsigned bdst, int kcol) {
#pragma unroll
        for (int i = 0; i < 8; i++) {
            int G = tid + i * 128;
            int r = G >> 3, c = G & 7;
            int row = q0 + r; row = (row < NQ) ? row : (NQ - 1);
            int col = kcol + c * 4; col = (col <= NKV - 4) ? col : (NKV - 4);
            cp16(bdst + r * 144 + c * 16, rpb + (size_t)row * NKV + col);
        }
    };

    {
#pragma unroll
        for (int i = 0; i < 8; i++) {
            int idx = tid + i * 128;
            if (idx < 512) {
                int r = idx >> 3, c = idx & 7;
                cp16(kd_base + r * 144 + c * 16, kb + idx * 4);
            } else {
                int j = idx - 512;
                int dst = (j >> 7) * 129 + ((j & 127) ^ ((j >> 3) & 3));
                cp16(vd_base + dst * 16, vb + j * 4);
            }
        }
    }
    cp_commit();
    stage_bias(bd_base, 0);
    cp_commit();

    for (int tt = 0; tt < 13; tt++) {
        const int buf = tt & 1;
        cp_wait0();
        __syncthreads();

        const float* Ksm = dsm + buf * 2304;
        const float* Vsm = dsm + VS_F + buf * 2064;
        const float* BsA = dsm + BS_F;
        const float* BsB = dsm + BS_F + 4608;

        if (tt < NFULL) {
            stage_bias(bd_base + 4608 * 4, tt * TN + 32);
            cp_commit();
            {
                const int nb = buf ^ 1;
                const unsigned kd = kd_base + nb * 9216;
                const unsigned vd = vd_base + nb * 8256;
                const float* kg = kb + (size_t)(tt + 1) * 2048;
                const float* vg = vb + (size_t)(tt + 1) * 2048;
                if (tt + 1 < NFULL) {
#pragma unroll
                    for (int i = 0; i < 8; i++) {
                        int idx = tid + i * 128;
                        if (idx < 512) {
                            int r = idx >> 3, c = idx & 7;
                            cp16(kd + r * 144 + c * 16, kg + idx * 4);
                        } else {
                            int j = idx - 512;
                            int dst = (j >> 7) * 129 + ((j & 127) ^ ((j >> 3) & 3));
                            cp16(vd + dst * 16, vg + j * 4);
                        }
                    }
                } else {
#pragma unroll
                    for (int i = 0; i < 2; i++) {
                        int idx = tid + i * 128;
                        if (idx < 128) {
                            int r = idx >> 3, c = idx & 7;
                            cp16(kd + r * 144 + c * 16, kg + idx * 4);
                        } else {
                            int j = idx - 128;
                            int grp = j >> 5, d = j & 31;
                            int dst = grp * 129 + ((d << 2) ^ ((d >> 1) & 3));
                            cp16(vd + dst * 16, vg + grp * 512 + d * 16);
                        }
                    }
                }
            }
            cp_commit();

            half_body<4>(Ksm, Vsm, BsA, qreg, o, sums, 0, g, t, w);

            cp_wait1();
            __syncthreads();

            stage_bias(bd_base, (tt + 1) * TN);
            cp_commit();

            half_body<4>(Ksm, Vsm, BsB, qreg, o, sums, 4, g, t, w);
        } else {
            half_body<2>(Ksm, Vsm, BsA, qreg, o, sums, 0, g, t, w);
        }
    }

    float inv[4];
#pragma unroll
    for (int rr = 0; rr < 4; rr++) {
        float s = sums[rr];
        s += __shfl_xor_sync(0xffffffffu, s, 1);
        s += __shfl_xor_sync(0xffffffffu, s, 2);
        inv[rr] = 1.f / s;
    }
#pragma unroll
    for (int mf = 0; mf < 2; mf++) {
#pragma unroll
        for (int rh = 0; rh < 2; rh++) {
            int rr = 2 * mf + rh;
            int qg = qraw[rr];
            if (qg >= NQ) continue;
            float* op = out + ((size_t)(b * NQ + qg)) * CC + h * 32 + 2 * t;
#pragma unroll
            for (int nf = 0; nf < 4; nf++) {
                float2 val = make_float2(o[mf][nf][2 * rh] * inv[rr],
                                         o[mf][nf][2 * rh + 1] * inv[rr]);
                *(float2*)(op + 8 * nf) = val;
            }
        }
    }
}

// ---------------- launch ----------------
extern "C" void kernel_launch(void* const* d_in, const int* in_sizes, int n_in,
                              void* d_out, int out_size)
{
    const float* x      = (const float*)d_in[0];
    const float* relpos = (const float*)d_in[1];
    const float* Wq     = (const float*)d_in[2];
    const float* bq     = (const float*)d_in[3];
    const float* Wk     = (const float*)d_in[4];
    const float* bk     = (const float*)d_in[5];
    const float* Wv     = (const float*)d_in[6];
    const float* bv     = (const float*)d_in[7];
    const float* cw     = (const float*)d_in[8];
    const float* cb     = (const float*)d_in[9];
    const float* gamma  = (const float*)d_in[10];
    const float* beta   = (const float*)d_in[11];
    const float* mean   = (const float*)d_in[12];
    const float* var    = (const float*)d_in[13];
    const float* Wp     = (const float*)d_in[14];
    const float* bp     = (const float*)d_in[15];
    float* out = (float*)d_out;

    float *q, *k, *v, *xr, *ao;
    cudaGetSymbolAddress((void**)&q,  g_q);
    cudaGetSymbolAddress((void**)&k,  g_k);
    cudaGetSymbolAddress((void**)&v,  g_v);
    cudaGetSymbolAddress((void**)&xr, g_xr);
    cudaGetSymbolAddress((void**)&ao, g_ao);

    cudaFuncSetAttribute(attn_mma_kernel,
                         cudaFuncAttributeMaxDynamicSharedMemorySize, SMEM_ATTN_B);
    cudaFuncSetAttribute(qproj_conv_kernel,
                         cudaFuncAttributeMaxDynamicSharedMemorySize, PROJ_SMEM_B);
    cudaFuncSetAttribute(kvproj_kernel,
                         cudaFuncAttributeMaxDynamicSharedMemorySize, PROJ_SMEM_B);
    cudaFuncSetAttribute(oproj_kernel,
                         cudaFuncAttributeMaxDynamicSharedMemorySize, PROJ_SMEM_B);

    // 1) fused q projection (cp.async staged) + spatial-reduction conv
    int conv_blocks = (BB * NKV * CC + 255) / 256;
    qproj_conv_kernel<<<QPB64 + conv_blocks, 256, PROJ_SMEM_B>>>(
        x, Wq, bq, q, cw, cb, gamma, beta, mean, var, xr);
    // 2) fused k+v projections
    kvproj_kernel<<<2 * KVB64, 256, PROJ_SMEM_B>>>(xr, Wk, bk, k, Wv, bv, v);
    // probe: keeps ncu capture slot on the attention kernel
    probe_kernel<<<1, 32>>>();
    // 3) attention: 4 warps x 32 q, split QK chains, hoisted addresses
    dim3 ag((NQ + 127) / 128, HEADS, BB);
    attn_mma_kernel<<<ag, 128, SMEM_ATTN_B>>>(q, k, v, relpos, ao);
    // 4) output projection
    oproj_kernel<<<QPB64, 256, PROJ_SMEM_B>>>(ao, Wp, bp, out);
}